// round 13
// baseline (speedup 1.0000x reference)
#include <cuda_runtime.h>
#include <cuda_fp16.h>
#include <cstdint>

#define NGRAPH 2048
#define NPG 91
#define DIM 128
#define ORDER 3

// scratch
__device__ float    g_fvb[ORDER * NGRAPH * DIM];     // fv + bu (3 MB)
__device__ uint32_t g_wuth[ORDER * 128 * 68];        // Wu^T fp16, padded (stride 136 halves)

// ---------------- kernel 1: fvb (blocks 0..767) + prep Wu^T (blocks 768..770)
__global__ void __launch_bounds__(128) prep_kernel(const float* __restrict__ feats,
                                                   const float* __restrict__ Wu,
                                                   const float* __restrict__ Wv,
                                                   const float* __restrict__ bu,
                                                   const int* __restrict__ last_idx) {
    if (blockIdx.x >= 768) {
        int o = blockIdx.x - 768;
        const float* w = Wu + o * DIM * DIM;
        for (int i = threadIdx.x; i < 64 * 128; i += 128) {
            int d2 = i & 63, n = i >> 6;
            float a = w[(2 * d2) * DIM + n];
            float b = w[(2 * d2 + 1) * DIM + n];
            __half2 p = __floats2half2_rn(a, b);
            g_wuth[o * 128 * 68 + n * 68 + d2] = *(uint32_t*)&p;
        }
        return;
    }
    const int GPB = 8;
    int o  = blockIdx.x / (NGRAPH / GPB);
    int b0 = (blockIdx.x % (NGRAPH / GPB)) * GPB;
    int h  = threadIdx.x;
    __shared__ float xs[GPB][DIM];
    #pragma unroll
    for (int j = 0; j < GPB; j++) {
        int node = last_idx[o * NGRAPH + b0 + j];
        xs[j][h] = feats[node * DIM + h];
    }
    __syncthreads();
    float acc[GPB];
    float bv = bu[o * DIM + h];
    #pragma unroll
    for (int j = 0; j < GPB; j++) acc[j] = bv;
    const float* Wvo = Wv + o * DIM * DIM;
    #pragma unroll 8
    for (int d = 0; d < DIM; d++) {
        float w = Wvo[d * DIM + h];
        #pragma unroll
        for (int j = 0; j < GPB; j++) acc[j] += xs[j][d] * w;
    }
    #pragma unroll
    for (int j = 0; j < GPB; j++)
        g_fvb[(o * NGRAPH + b0 + j) * DIM + h] = acc[j];
}

// ---------------- fused main kernel: 512 thr, 16 warps, 1 graph/CTA,
// ---------------- ALL 3 ORDERS in one k-loop pass (A fragments loaded once)
#define LDAH 136
#define OFF_A      0               // 96*136*2 = 26112 B
#define OFF_WUT    26112           // 3 * 34816 = 104448 -> 130560
#define WUT_STRIDE 34816
#define OFF_FV3    130560          // 384 floats -> 132096
#define OFF_WE3    132096          // 384 floats -> 133632
#define OFF_ER     133632          // 3*8*96 floats = 9216 B -> 142848
#define OFF_AL     142848          // 3*96 floats = 1152 B -> 144000
#define SMEM_BYTES 144000

__device__ __forceinline__ void ldsm_x4(uint32_t r[4], uint32_t saddr) {
    asm volatile("ldmatrix.sync.aligned.m8n8.x4.shared.b16 {%0,%1,%2,%3}, [%4];"
                 : "=r"(r[0]), "=r"(r[1]), "=r"(r[2]), "=r"(r[3])
                 : "r"(saddr));
}
__device__ __forceinline__ void mma_f16(float c[4], const uint32_t a[4],
                                        uint32_t b0, uint32_t b1) {
    asm volatile(
        "mma.sync.aligned.m16n8k16.row.col.f32.f16.f16.f32 "
        "{%0,%1,%2,%3}, {%4,%5,%6,%7}, {%8,%9}, {%0,%1,%2,%3};"
        : "+f"(c[0]), "+f"(c[1]), "+f"(c[2]), "+f"(c[3])
        : "r"(a[0]), "r"(a[1]), "r"(a[2]), "r"(a[3]), "r"(b0), "r"(b1));
}

__global__ void __launch_bounds__(512, 1) fused_kernel(const float* __restrict__ feats,
                                                       const float* __restrict__ We,
                                                       const float* __restrict__ fvb,
                                                       float* __restrict__ out) {
    extern __shared__ char smc[];
    uint2*  sA2  = (uint2*)(smc + OFF_A);
    float*  sFV3 = (float*)(smc + OFF_FV3);
    float*  sWe3 = (float*)(smc + OFF_WE3);
    float*  sER  = (float*)(smc + OFF_ER);
    float*  sAL  = (float*)(smc + OFF_AL);
    const __half* sAh = (const __half*)(smc + OFF_A);

    const int tid   = threadIdx.x;
    const int graph = blockIdx.x;
    const int lane  = tid & 31;
    const int wid   = tid >> 5;
    const int warpM = wid >> 3;           // 0..1 -> 48 rows
    const int warpN = wid & 7;            // 0..7 -> 16 cols
    const int gid   = lane >> 2;
    const int tig   = lane & 3;

    // stage feats as fp16: 91 rows + 5 zero pad rows
    {
        const float4* f4 = (const float4*)(feats + (size_t)graph * NPG * DIM);
        for (int i = tid; i < NPG * 32; i += 512) {
            int r = i >> 5, c = i & 31;
            float4 v = f4[i];
            __half2 p0 = __floats2half2_rn(v.x, v.y);
            __half2 p1 = __floats2half2_rn(v.z, v.w);
            sA2[r * 34 + c] = make_uint2(*(uint32_t*)&p0, *(uint32_t*)&p1);
        }
        if (tid < 5 * 32) {
            int r = NPG + (tid >> 5), c = tid & 31;
            sA2[r * 34 + c] = make_uint2(0u, 0u);
        }
        if (tid < 384) {
            int o = tid >> 7, h = tid & 127;
            sFV3[tid] = fvb[(o * NGRAPH + graph) * DIM + h];
            sWe3[tid] = We[tid];
        }
        // all 3 WuT images
        const float4* src = (const float4*)g_wuth;
        float4* dst = (float4*)(smc + OFF_WUT);
        #pragma unroll
        for (int i = 0; i < 13; i++) {
            int j = tid + i * 512;
            if (j < 6528) dst[j] = src[j];
        }
    }

    // ldmatrix base addresses (verified mapping from R9)
    uint32_t aBase[3];
    #pragma unroll
    for (int mt = 0; mt < 3; mt++) {
        const __half* p = sAh + (warpM * 48 + mt * 16 + (lane & 15)) * LDAH
                        + ((lane >> 4) << 3);
        aBase[mt] = (uint32_t)__cvta_generic_to_shared(p);
    }
    uint32_t bBase[3];
    {
        const __half* p = (const __half*)(smc + OFF_WUT)
            + (warpN * 16 + ((lane >> 4) << 3) + (lane & 7)) * LDAH
            + (((lane >> 3) & 1) << 3);
        uint32_t b0 = (uint32_t)__cvta_generic_to_shared(p);
        bBase[0] = b0;
        bBase[1] = b0 + WUT_STRIDE;
        bBase[2] = b0 + 2 * WUT_STRIDE;
    }
    __syncthreads();   // B0: staging complete

    // ---- single k-loop for all 3 orders ----
    float acc[3][3][2][4];
    #pragma unroll
    for (int o = 0; o < 3; o++)
        #pragma unroll
        for (int mt = 0; mt < 3; mt++)
            #pragma unroll
            for (int nt = 0; nt < 2; nt++)
                #pragma unroll
                for (int q = 0; q < 4; q++) acc[o][mt][nt][q] = 0.f;

    #pragma unroll
    for (int ks = 0; ks < 8; ks++) {
        const uint32_t kb = (uint32_t)(ks * 32);
        uint32_t afr[3][4];
        #pragma unroll
        for (int mt = 0; mt < 3; mt++) ldsm_x4(afr[mt], aBase[mt] + kb);
        uint32_t bfr[3][4];
        #pragma unroll
        for (int o = 0; o < 3; o++) ldsm_x4(bfr[o], bBase[o] + kb);
        #pragma unroll
        for (int o = 0; o < 3; o++)
            #pragma unroll
            for (int mt = 0; mt < 3; mt++) {
                mma_f16(acc[o][mt][0], afr[mt], bfr[o][0], bfr[o][1]);
                mma_f16(acc[o][mt][1], afr[mt], bfr[o][2], bfr[o][3]);
            }
    }

    // ---- epilogue: e-row partials for all 3 orders ----
    #pragma unroll
    for (int o = 0; o < 3; o++) {
        const float* sFV = sFV3 + o * DIM;
        const float* sWe = sWe3 + o * DIM;
        #pragma unroll
        for (int mt = 0; mt < 3; mt++) {
            int m0 = warpM * 48 + mt * 16 + gid;
            int m1 = m0 + 8;
            float e0 = 0.f, e1 = 0.f;
            #pragma unroll
            for (int nt = 0; nt < 2; nt++) {
                int h = warpN * 16 + nt * 8 + tig * 2;
                float we0 = sWe[h], we1 = sWe[h + 1];
                if (m0 < NPG) {
                    float x0 = 0.5f * (acc[o][mt][nt][0] + sFV[h]);
                    float x1 = 0.5f * (acc[o][mt][nt][1] + sFV[h + 1]);
                    float t0, t1;
                    asm("tanh.approx.f32 %0, %1;" : "=f"(t0) : "f"(x0));
                    asm("tanh.approx.f32 %0, %1;" : "=f"(t1) : "f"(x1));
                    e0 += we0 * (0.5f * t0 + 0.5f) + we1 * (0.5f * t1 + 0.5f);
                }
                if (m1 < NPG) {
                    float x2 = 0.5f * (acc[o][mt][nt][2] + sFV[h]);
                    float x3 = 0.5f * (acc[o][mt][nt][3] + sFV[h + 1]);
                    float t2, t3;
                    asm("tanh.approx.f32 %0, %1;" : "=f"(t2) : "f"(x2));
                    asm("tanh.approx.f32 %0, %1;" : "=f"(t3) : "f"(x3));
                    e1 += we0 * (0.5f * t2 + 0.5f) + we1 * (0.5f * t3 + 0.5f);
                }
            }
            e0 += __shfl_xor_sync(0xffffffffu, e0, 1);
            e0 += __shfl_xor_sync(0xffffffffu, e0, 2);
            e1 += __shfl_xor_sync(0xffffffffu, e1, 1);
            e1 += __shfl_xor_sync(0xffffffffu, e1, 2);
            if (tig == 0) {
                if (m0 < NPG) sER[o * 768 + warpN * 96 + m0] = e0;
                if (m1 < NPG) sER[o * 768 + warpN * 96 + m1] = e1;
            }
        }
    }
    __syncthreads();   // B1: sER complete

    // ---- 3 softmaxes in parallel (warps 0,1,2) ----
    if (wid < 3) {
        const float* er = sER + wid * 768;
        float ev[3];
        #pragma unroll
        for (int j = 0; j < 3; j++) {
            int r = lane + 32 * j;
            if (r < NPG) {
                float s = 0.f;
                #pragma unroll
                for (int bk = 0; bk < 8; bk++) s += er[bk * 96 + r];
                ev[j] = s;
            } else ev[j] = -1e30f;
        }
        float mx = fmaxf(ev[0], fmaxf(ev[1], ev[2]));
        #pragma unroll
        for (int s = 16; s; s >>= 1)
            mx = fmaxf(mx, __shfl_xor_sync(0xffffffffu, mx, s));
        float sum = 0.f;
        #pragma unroll
        for (int j = 0; j < 3; j++) {
            ev[j] = (lane + 32 * j < NPG) ? __expf(ev[j] - mx) : 0.f;
            sum += ev[j];
        }
        #pragma unroll
        for (int s = 16; s; s >>= 1)
            sum += __shfl_xor_sync(0xffffffffu, sum, s);
        float inv = 1.f / sum;
        #pragma unroll
        for (int j = 0; j < 3; j++) {
            int r = lane + 32 * j;
            if (r < NPG) sAL[wid * 96 + r] = ev[j] * inv;
        }
    }
    __syncthreads();   // B2: sAL ready

    // ---- tail: rst[graph,o,:] = sum_m alpha[o][m] * feats_h[m,:] ----
    if (tid < 384) {
        int o = tid >> 7, h = tid & 127;
        const float*  alB = sAL + o * 96;
        const __half* aB  = sAh + h;
        float r0 = 0.f;
        #pragma unroll 7
        for (int r = 0; r < NPG; r++)
            r0 += alB[r] * __half2float(aB[r * LDAH]);
        out[(graph * ORDER + o) * DIM + h] = r0;
    }
}

extern "C" void kernel_launch(void* const* d_in, const int* in_sizes, int n_in,
                              void* d_out, int out_size) {
    const float* feats    = (const float*)d_in[0];
    const float* Wu       = (const float*)d_in[1];
    const float* bu       = (const float*)d_in[2];
    const float* Wv       = (const float*)d_in[3];
    const float* We       = (const float*)d_in[4];
    const int*   last_idx = (const int*)d_in[6];
    float* out = (float*)d_out;

    prep_kernel<<<768 + ORDER, 128>>>(feats, Wu, Wv, bu, last_idx);

    const float* fvb_ptr;
    cudaGetSymbolAddress((void**)&fvb_ptr, g_fvb);

    cudaFuncSetAttribute(fused_kernel, cudaFuncAttributeMaxDynamicSharedMemorySize,
                         SMEM_BYTES);
    fused_kernel<<<NGRAPH, 512, SMEM_BYTES>>>(feats, We, fvb_ptr, out);
}

// round 14
// speedup vs baseline: 1.0312x; 1.0312x over previous
#include <cuda_runtime.h>
#include <cuda_fp16.h>
#include <cstdint>

#define NGRAPH 2048
#define NPG 91
#define DIM 128
#define ORDER 3

// scratch
__device__ float    g_fvb[ORDER * NGRAPH * DIM];     // 0.5*(fv + bu) (3 MB)
__device__ uint32_t g_wuth[ORDER * 128 * 68];        // Wu^T fp16, padded (stride 136 halves)

// ---------------- prep: fvb (blocks 0..191, GPB=32) + Wu^T (blocks 192..194)
#define PGPB 32
__global__ void __launch_bounds__(256) prep_kernel(const float* __restrict__ feats,
                                                   const float* __restrict__ Wu,
                                                   const float* __restrict__ Wv,
                                                   const float* __restrict__ bu,
                                                   const int* __restrict__ last_idx) {
    if (blockIdx.x >= 192) {
        int o = blockIdx.x - 192;
        const float* w = Wu + o * DIM * DIM;
        for (int i = threadIdx.x; i < 64 * 128; i += 256) {
            int d2 = i & 63, n = i >> 6;
            float a = w[(2 * d2) * DIM + n];
            float b = w[(2 * d2 + 1) * DIM + n];
            __half2 p = __floats2half2_rn(a, b);
            g_wuth[o * 128 * 68 + n * 68 + d2] = *(uint32_t*)&p;
        }
        return;
    }
    int o   = blockIdx.x >> 6;                 // 64 blocks per order
    int b0  = (blockIdx.x & 63) * PGPB;        // 32 graphs per block
    int grp = threadIdx.x >> 7;                // 0/1: 16 graphs each
    int h   = threadIdx.x & 127;
    __shared__ float xs[PGPB][DIM];
    #pragma unroll
    for (int j = 0; j < 16; j++) {
        int row = grp * 16 + j;
        int node = last_idx[o * NGRAPH + b0 + row];
        xs[row][h] = feats[(size_t)node * DIM + h];
    }
    __syncthreads();
    float acc[16];
    float bv = bu[o * DIM + h];
    #pragma unroll
    for (int j = 0; j < 16; j++) acc[j] = bv;
    const float* Wvo = Wv + o * DIM * DIM;
    #pragma unroll 4
    for (int d = 0; d < DIM; d++) {
        float w = Wvo[d * DIM + h];
        #pragma unroll
        for (int j = 0; j < 16; j++) acc[j] += xs[grp * 16 + j][d] * w;
    }
    #pragma unroll
    for (int j = 0; j < 16; j++)
        g_fvb[(o * NGRAPH + b0 + grp * 16 + j) * DIM + h] = 0.5f * acc[j];
}

// ---------------- fused main kernel (512 threads, 16 warps, 1 graph/CTA) ----
// A: 96 rows x 128 halves, stride 136 halves. WuT: double-buffered.
#define LDAH 136
#define OFF_A    0                        // 96*136*2 = 26112 B
#define OFF_WUT  26112                    // 2 x 34816 B -> end 95744
#define WUT_BUFB 34816
#define OFF_FV3  95744                    // 384 floats -> end 97280
#define OFF_WE3  97280                    // 384 floats -> end 98816
#define OFF_ER   98816                    // 8*96 floats = 3072 B -> end 101888
#define OFF_AL   101888                   // 96 floats -> end 102272
#define OFF_TP   102272                   // 384 floats -> 103808
#define SMEM_BYTES 103808                 // x2 CTAs = 207616 <= 227KB

__device__ __forceinline__ void ldsm_x4(uint32_t r[4], uint32_t saddr) {
    asm volatile("ldmatrix.sync.aligned.m8n8.x4.shared.b16 {%0,%1,%2,%3}, [%4];"
                 : "=r"(r[0]), "=r"(r[1]), "=r"(r[2]), "=r"(r[3])
                 : "r"(saddr));
}
__device__ __forceinline__ void mma_f16(float c[4], const uint32_t a[4],
                                        uint32_t b0, uint32_t b1) {
    asm volatile(
        "mma.sync.aligned.m16n8k16.row.col.f32.f16.f16.f32 "
        "{%0,%1,%2,%3}, {%4,%5,%6,%7}, {%8,%9}, {%0,%1,%2,%3};"
        : "+f"(c[0]), "+f"(c[1]), "+f"(c[2]), "+f"(c[3])
        : "r"(a[0]), "r"(a[1]), "r"(a[2]), "r"(a[3]), "r"(b0), "r"(b1));
}

__global__ void __launch_bounds__(512, 2) fused_kernel(const float* __restrict__ feats,
                                                       const float* __restrict__ We,
                                                       const float* __restrict__ fvb,
                                                       float* __restrict__ out) {
    extern __shared__ char smc[];
    uint2*  sA2   = (uint2*)(smc + OFF_A);
    float*  sFV3  = (float*)(smc + OFF_FV3);
    float*  sWe3  = (float*)(smc + OFF_WE3);
    float*  sER   = (float*)(smc + OFF_ER);
    float*  sAL   = (float*)(smc + OFF_AL);
    float*  sTP   = (float*)(smc + OFF_TP);
    const __half* sAh = (const __half*)(smc + OFF_A);

    const int tid   = threadIdx.x;
    const int graph = blockIdx.x;
    const int lane  = tid & 31;
    const int wid   = tid >> 5;
    const int warpM = wid >> 3;           // 0..1 -> 48 rows
    const int warpN = wid & 7;            // 0..7 -> 16 cols
    const int gid   = lane >> 2;
    const int tig   = lane & 3;

    // stage feats as fp16: 91 rows + 5 zero pad rows
    {
        const float4* f4 = (const float4*)(feats + (size_t)graph * NPG * DIM);
        for (int i = tid; i < NPG * 32; i += 512) {
            int r = i >> 5, c = i & 31;
            float4 v = f4[i];
            __half2 p0 = __floats2half2_rn(v.x, v.y);
            __half2 p1 = __floats2half2_rn(v.z, v.w);
            sA2[r * 34 + c] = make_uint2(*(uint32_t*)&p0, *(uint32_t*)&p1);
        }
        if (tid < 5 * 32) {
            int r = NPG + (tid >> 5), c = tid & 31;
            sA2[r * 34 + c] = make_uint2(0u, 0u);
        }
        // all orders' halved fv and halved We upfront
        if (tid < 384) {
            int o = tid >> 7, h = tid & 127;
            sFV3[tid] = fvb[(o * NGRAPH + graph) * DIM + h];   // already 0.5*(fv+bu)
            sWe3[tid] = 0.5f * We[tid];
        }
        // WuT[0] into buffer 0
        const float4* src = (const float4*)g_wuth;
        float4* dst = (float4*)(smc + OFF_WUT);
        for (int i = tid; i < 2176; i += 512) dst[i] = src[i];
    }

    // ldmatrix base addresses
    uint32_t aBase[3];
    #pragma unroll
    for (int mt = 0; mt < 3; mt++) {
        const __half* p = sAh + (warpM * 48 + mt * 16 + (lane & 15)) * LDAH
                        + ((lane >> 4) << 3);
        aBase[mt] = (uint32_t)__cvta_generic_to_shared(p);
    }
    uint32_t bBase;
    {
        const __half* p = (const __half*)(smc + OFF_WUT)
            + (warpN * 16 + ((lane >> 4) << 3) + (lane & 7)) * LDAH
            + (((lane >> 3) & 1) << 3);
        bBase = (uint32_t)__cvta_generic_to_shared(p);
    }
    __syncthreads();

    for (int o = 0; o < ORDER; o++) {
        const uint32_t bufOff = (uint32_t)((o & 1) * WUT_BUFB);
        float acc[3][2][4];
        #pragma unroll
        for (int mt = 0; mt < 3; mt++)
            #pragma unroll
            for (int nt = 0; nt < 2; nt++) {
                acc[mt][nt][0] = 0.f; acc[mt][nt][1] = 0.f;
                acc[mt][nt][2] = 0.f; acc[mt][nt][3] = 0.f;
            }

        #pragma unroll
        for (int ks = 0; ks < 8; ks++) {
            const uint32_t kb = (uint32_t)(ks * 32);
            uint32_t afr[3][4];
            #pragma unroll
            for (int mt = 0; mt < 3; mt++) ldsm_x4(afr[mt], aBase[mt] + kb);
            uint32_t bfr[4];
            ldsm_x4(bfr, bBase + bufOff + kb);
            #pragma unroll
            for (int mt = 0; mt < 3; mt++) {
                mma_f16(acc[mt][0], afr[mt], bfr[0], bfr[1]);
                mma_f16(acc[mt][1], afr[mt], bfr[2], bfr[3]);
            }
        }

        // epilogue: e-row partials.  sigmoid(y) = 0.5*tanh(0.5y)+0.5;
        // e = sum we*(0.5t+0.5) = sum we'*t + sum we'   (we' = 0.5we, pre-staged)
        const float* sFV = sFV3 + o * DIM;   // 0.5*(fv+bu)
        const float* sWe = sWe3 + o * DIM;   // 0.5*We
        int hA = warpN * 16 + tig * 2;       // nt=0 pair
        int hB = hA + 8;                     // nt=1 pair
        float weA0 = sWe[hA], weA1 = sWe[hA + 1];
        float weB0 = sWe[hB], weB1 = sWe[hB + 1];
        float fvA0 = sFV[hA], fvA1 = sFV[hA + 1];
        float fvB0 = sFV[hB], fvB1 = sFV[hB + 1];
        float cst  = weA0 + weA1 + weB0 + weB1;
        #pragma unroll
        for (int mt = 0; mt < 3; mt++) {
            int m0 = warpM * 48 + mt * 16 + gid;
            int m1 = m0 + 8;
            float e0 = cst, e1 = cst;
            {
                float x0 = fmaf(0.5f, acc[mt][0][0], fvA0);
                float x1 = fmaf(0.5f, acc[mt][0][1], fvA1);
                float x2 = fmaf(0.5f, acc[mt][1][0], fvB0);
                float x3 = fmaf(0.5f, acc[mt][1][1], fvB1);
                float t0, t1, t2, t3;
                asm("tanh.approx.f32 %0, %1;" : "=f"(t0) : "f"(x0));
                asm("tanh.approx.f32 %0, %1;" : "=f"(t1) : "f"(x1));
                asm("tanh.approx.f32 %0, %1;" : "=f"(t2) : "f"(x2));
                asm("tanh.approx.f32 %0, %1;" : "=f"(t3) : "f"(x3));
                e0 = fmaf(weA0, t0, e0); e0 = fmaf(weA1, t1, e0);
                e0 = fmaf(weB0, t2, e0); e0 = fmaf(weB1, t3, e0);
            }
            {
                float x0 = fmaf(0.5f, acc[mt][0][2], fvA0);
                float x1 = fmaf(0.5f, acc[mt][0][3], fvA1);
                float x2 = fmaf(0.5f, acc[mt][1][2], fvB0);
                float x3 = fmaf(0.5f, acc[mt][1][3], fvB1);
                float t0, t1, t2, t3;
                asm("tanh.approx.f32 %0, %1;" : "=f"(t0) : "f"(x0));
                asm("tanh.approx.f32 %0, %1;" : "=f"(t1) : "f"(x1));
                asm("tanh.approx.f32 %0, %1;" : "=f"(t2) : "f"(x2));
                asm("tanh.approx.f32 %0, %1;" : "=f"(t3) : "f"(x3));
                e1 = fmaf(weA0, t0, e1); e1 = fmaf(weA1, t1, e1);
                e1 = fmaf(weB0, t2, e1); e1 = fmaf(weB1, t3, e1);
            }
            e0 += __shfl_xor_sync(0xffffffffu, e0, 1);
            e0 += __shfl_xor_sync(0xffffffffu, e0, 2);
            e1 += __shfl_xor_sync(0xffffffffu, e1, 1);
            e1 += __shfl_xor_sync(0xffffffffu, e1, 2);
            if (tig == 0) {
                if (m0 < NPG) sER[warpN * 96 + m0] = e0;
                if (m1 < NPG) sER[warpN * 96 + m1] = e1;
            }
        }

        // stage next order's WuT into the other buffer (off critical path)
        if (o < ORDER - 1) {
            const float4* src = (const float4*)(g_wuth + (o + 1) * 128 * 68);
            float4* dst = (float4*)(smc + OFF_WUT + ((o + 1) & 1) * WUT_BUFB);
            for (int i = tid; i < 2176; i += 512) dst[i] = src[i];
        }
        __syncthreads();   // B1: sER complete

        // softmax over 91 nodes (warp 0)
        if (wid == 0) {
            float ev[3];
            #pragma unroll
            for (int j = 0; j < 3; j++) {
                int r = lane + 32 * j;
                if (r < NPG) {
                    float s = 0.f;
                    #pragma unroll
                    for (int bk = 0; bk < 8; bk++) s += sER[bk * 96 + r];
                    ev[j] = s;
                } else ev[j] = -1e30f;
            }
            float mx = fmaxf(ev[0], fmaxf(ev[1], ev[2]));
            #pragma unroll
            for (int s = 16; s; s >>= 1)
                mx = fmaxf(mx, __shfl_xor_sync(0xffffffffu, mx, s));
            float sum = 0.f;
            #pragma unroll
            for (int j = 0; j < 3; j++) {
                ev[j] = (lane + 32 * j < NPG) ? __expf(ev[j] - mx) : 0.f;
                sum += ev[j];
            }
            #pragma unroll
            for (int s = 16; s; s >>= 1)
                sum += __shfl_xor_sync(0xffffffffu, sum, s);
            float inv = 1.f / sum;
            #pragma unroll
            for (int j = 0; j < 3; j++) {
                int r = lane + 32 * j;
                if (r < NPG) sAL[r] = ev[j] * inv;
            }
        }
        __syncthreads();   // B2: sAL ready

        // rst[graph,o,:] = sum_m alpha[m] * feats_h[m,:]  (4 row-parts)
        {
            int part = tid >> 7;          // 0..3
            int h    = tid & 127;
            int r0i  = part * 23;
            int cnt  = (part == 3) ? 22 : 23;
            const __half* aB  = sAh + r0i * LDAH + h;
            const float*  alB = sAL + r0i;
            float r0 = 0.f;
            #pragma unroll 23
            for (int r = 0; r < cnt; r++)
                r0 += alB[r] * __half2float(aB[r * LDAH]);
            if (part) sTP[(part - 1) * 128 + h] = r0;
            __syncthreads();   // B3: partials ready
            if (!part)
                out[(graph * ORDER + o) * DIM + h] =
                    r0 + sTP[h] + sTP[128 + h] + sTP[256 + h];
        }
    }
}

extern "C" void kernel_launch(void* const* d_in, const int* in_sizes, int n_in,
                              void* d_out, int out_size) {
    const float* feats    = (const float*)d_in[0];
    const float* Wu       = (const float*)d_in[1];
    const float* bu       = (const float*)d_in[2];
    const float* Wv       = (const float*)d_in[3];
    const float* We       = (const float*)d_in[4];
    const int*   last_idx = (const int*)d_in[6];
    float* out = (float*)d_out;

    prep_kernel<<<192 + ORDER, 256>>>(feats, Wu, Wv, bu, last_idx);

    const float* fvb_ptr;
    cudaGetSymbolAddress((void**)&fvb_ptr, g_fvb);

    cudaFuncSetAttribute(fused_kernel, cudaFuncAttributeMaxDynamicSharedMemorySize,
                         SMEM_BYTES);
    fused_kernel<<<NGRAPH, 512, SMEM_BYTES>>>(feats, We, fvb_ptr, out);
}